// round 6
// baseline (speedup 1.0000x reference)
#include <cuda_runtime.h>
#include <cuda_bf16.h>
#include <math.h>
#include <stddef.h>
#include <stdint.h>

// ---------------------------------------------------------------------------
// Problem constants
// ---------------------------------------------------------------------------
#define BATCH   2
#define SEQL    2048
#define DIM     4096
#define NH      32
#define NKV     8
#define HEADD   128
#define HIDDEN  11008
#define TOK     (BATCH * SEQL)        /* 4096 */
#define QD      (NH  * HEADD)         /* 4096 */
#define KVD     (NKV * HEADD)         /* 1024 */
#define MAXEL   ((size_t)TOK * HIDDEN)

// ---------------------------------------------------------------------------
// Scratch (static device globals; allocation-free per harness rules)
// ---------------------------------------------------------------------------
__device__ float g_q [(size_t)TOK * QD];
__device__ float g_k [(size_t)TOK * KVD];
__device__ float g_v [(size_t)TOK * KVD];
__device__ float g_h [(size_t)TOK * DIM];
__device__ float g_f1[(size_t)TOK * HIDDEN];
__device__ float g_f3[(size_t)TOK * HIDDEN];
__device__ __nv_bfloat16 g_ahi[MAXEL];
__device__ __nv_bfloat16 g_alo[MAXEL];
__device__ __nv_bfloat16 g_whi[MAXEL];
__device__ __nv_bfloat16 g_wlo[MAXEL];

// ---------------------------------------------------------------------------
// PTX helpers (sm_100-safe: cp.async / ldmatrix / mma.sync only)
// ---------------------------------------------------------------------------
__device__ __forceinline__ uint32_t smem_u32(const void* p) {
    uint32_t a;
    asm("{ .reg .u64 t; cvta.to.shared.u64 t, %1; cvt.u32.u64 %0, t; }"
        : "=r"(a) : "l"(p));
    return a;
}
#define CP_ASYNC16(dst, src) \
    asm volatile("cp.async.cg.shared.global [%0], [%1], 16;" \
                 :: "r"(dst), "l"(src) : "memory")
#define CP_COMMIT() asm volatile("cp.async.commit_group;" ::: "memory")
#define CP_WAIT0()  asm volatile("cp.async.wait_group 0;" ::: "memory")
#define CP_WAIT1()  asm volatile("cp.async.wait_group 1;" ::: "memory")
#define CP_WAIT2()  asm volatile("cp.async.wait_group 2;" ::: "memory")

#define LDMX4(r0, r1, r2, r3, addr) \
    asm volatile("ldmatrix.sync.aligned.m8n8.x4.shared.b16 {%0,%1,%2,%3}, [%4];" \
                 : "=r"(r0), "=r"(r1), "=r"(r2), "=r"(r3) : "r"(addr))

#define MMA16816(c0, c1, c2, c3, a0, a1, a2, a3, b0, b1) \
    asm volatile("mma.sync.aligned.m16n8k16.row.col.f32.bf16.bf16.f32 " \
                 "{%0,%1,%2,%3}, {%4,%5,%6,%7}, {%8,%9}, {%0,%1,%2,%3};" \
                 : "+f"(c0), "+f"(c1), "+f"(c2), "+f"(c3) \
                 : "r"(a0), "r"(a1), "r"(a2), "r"(a3), "r"(b0), "r"(b1))

// ---------------------------------------------------------------------------
// bf16 HMMA GEMM: C[M,N] = sum of 3 passes (Ahi*Bhi + Ahi*Blo + Alo*Bhi) + resid
// A*: [M,K] bf16 row-major. B*: [N,K] bf16 row-major (W^T, K-major = mma .col).
// 128x128 CTA tile, 256 thr (8 warps, 2Mx4N), BK=64.
// 4-stage cp.async ring (128 KB smem), ONE __syncthreads per K-chunk,
// next-chunk loads issued before the MMA body for copy/compute overlap.
// ---------------------------------------------------------------------------
#define STG 32768                 /* bytes per stage (A 16K + B 16K) */
#define NSTAGE 4
#define GEMM_SMEM (STG * NSTAGE)  /* 131072 */

__global__ void __launch_bounds__(256) mma_gemm(
    const __nv_bfloat16* __restrict__ Ahi, const __nv_bfloat16* __restrict__ Alo,
    const __nv_bfloat16* __restrict__ Bhi, const __nv_bfloat16* __restrict__ Blo,
    const float* __restrict__ resid, float* __restrict__ C,
    int K, int ldc)
{
    extern __shared__ char smc[];
    const uint32_t sbase = smem_u32(smc);
    const int tid   = threadIdx.x;
    const int lane  = tid & 31;
    const int wid   = tid >> 5;
    const int warpM = wid >> 2;          // 0..1
    const int warpN = wid & 3;           // 0..3
    const int m0 = blockIdx.y * 128;
    const int n0 = blockIdx.x * 128;

    const int nk = K >> 6;               // 64-wide K chunks per pass
    const int NC = 3 * nk;

    float acc[4][4][4];
#pragma unroll
    for (int mt = 0; mt < 4; mt++)
#pragma unroll
        for (int nt = 0; nt < 4; nt++)
#pragma unroll
            for (int e = 0; e < 4; e++) acc[mt][nt][e] = 0.f;

    auto load_chunk = [&](int c, int stage) {
        const int p  = c / nk;
        const int k0 = (c - p * nk) << 6;
        const __nv_bfloat16* As = (p == 2) ? Alo : Ahi;
        const __nv_bfloat16* Bs = (p == 1) ? Blo : Bhi;
        const uint32_t uA = sbase + stage * STG;
        const uint32_t uB = uA + 16384;
#pragma unroll
        for (int it = 0; it < 4; it++) {
            const int idx = tid + it * 256;          // 0..1023
            const int r  = idx >> 3;                 // 0..127
            const int cc = idx & 7;                  // 16B column
            uint32_t o = (uint32_t)(r * 128 + cc * 16);
            o ^= (o >> 3) & 0x70;
            CP_ASYNC16(uA + o, As + (size_t)(m0 + r) * K + k0 + cc * 8);
            CP_ASYNC16(uB + o, Bs + (size_t)(n0 + r) * K + k0 + cc * 8);
        }
    };

    auto compute_chunk = [&](int stage) {
        const uint32_t uA = sbase + stage * STG;
        const uint32_t uB = uA + 16384;
#pragma unroll
        for (int ks = 0; ks < 4; ks++) {
            const int kb = ks * 32;                  // byte offset of k16 step
            uint32_t a[4][4];
#pragma unroll
            for (int mt = 0; mt < 4; mt++) {
                const int r = warpM * 64 + mt * 16 + (lane & 15);
                const int cbyte = kb + ((lane >> 4) << 4);
                uint32_t o = (uint32_t)(r * 128 + cbyte);
                o ^= (o >> 3) & 0x70;
                LDMX4(a[mt][0], a[mt][1], a[mt][2], a[mt][3], uA + o);
            }
            uint32_t bf[2][4];
#pragma unroll
            for (int g = 0; g < 2; g++) {
                const int r = warpN * 32 + g * 16 + (lane & 7) + ((lane >> 4) << 3);
                const int cbyte = kb + (((lane >> 3) & 1) << 4);
                uint32_t o = (uint32_t)(r * 128 + cbyte);
                o ^= (o >> 3) & 0x70;
                LDMX4(bf[g][0], bf[g][1], bf[g][2], bf[g][3], uB + o);
            }
#pragma unroll
            for (int mt = 0; mt < 4; mt++)
#pragma unroll
                for (int nt = 0; nt < 4; nt++) {
                    const uint32_t b0 = bf[nt >> 1][(nt & 1) * 2];
                    const uint32_t b1 = bf[nt >> 1][(nt & 1) * 2 + 1];
                    MMA16816(acc[mt][nt][0], acc[mt][nt][1],
                             acc[mt][nt][2], acc[mt][nt][3],
                             a[mt][0], a[mt][1], a[mt][2], a[mt][3], b0, b1);
                }
        }
    };

    // prologue: fill 3 of 4 stages
    load_chunk(0, 0); CP_COMMIT();
    load_chunk(1, 1); CP_COMMIT();
    load_chunk(2, 2); CP_COMMIT();

    for (int i = 0; i < NC; i++) {
        // stage i resident when <= 2 newer groups pending
        if (i < NC - 2)      { CP_WAIT2(); }
        else if (i == NC - 2){ CP_WAIT1(); }
        else                 { CP_WAIT0(); }
        __syncthreads();     // all warps see stage i; slot (i+3)&3 free
        if (i + 3 < NC) { load_chunk(i + 3, (i + 3) & (NSTAGE - 1)); CP_COMMIT(); }
        compute_chunk(i & (NSTAGE - 1));
    }

    // epilogue: direct global stores (+ optional residual)
    const int g  = lane >> 2;
    const int tg = lane & 3;
#pragma unroll
    for (int mt = 0; mt < 4; mt++) {
        const int row = m0 + warpM * 64 + mt * 16 + g;
#pragma unroll
        for (int nt = 0; nt < 4; nt++) {
            const int col = n0 + warpN * 32 + nt * 8 + tg * 2;
            const size_t i0 = (size_t)row * ldc + col;
            const size_t i1 = (size_t)(row + 8) * ldc + col;
            float2 v0 = make_float2(acc[mt][nt][0], acc[mt][nt][1]);
            float2 v1 = make_float2(acc[mt][nt][2], acc[mt][nt][3]);
            if (resid) {
                float2 r0 = *(const float2*)(resid + i0);
                float2 r1 = *(const float2*)(resid + i1);
                v0.x += r0.x; v0.y += r0.y;
                v1.x += r1.x; v1.y += r1.y;
            }
            *(float2*)(C + i0) = v0;
            *(float2*)(C + i1) = v1;
        }
    }
}

// ---------------------------------------------------------------------------
// fp32 -> bf16 hi/lo split (row-major, elementwise)
// ---------------------------------------------------------------------------
__global__ void split_kernel(const float* __restrict__ src,
                             __nv_bfloat16* __restrict__ hi,
                             __nv_bfloat16* __restrict__ lo, size_t n)
{
    const size_t stride = (size_t)gridDim.x * blockDim.x;
    for (size_t i = (size_t)blockIdx.x * blockDim.x + threadIdx.x; i < n; i += stride) {
        float v = src[i];
        __nv_bfloat16 h = __float2bfloat16(v);
        hi[i] = h;
        lo[i] = __float2bfloat16(v - __bfloat162float(h));
    }
}

// W [K,N] fp32 -> W^T [N,K] bf16 hi/lo.  grid=(N/32, K/32), block=(32,8)
__global__ void split_transpose_kernel(const float* __restrict__ W,
                                       __nv_bfloat16* __restrict__ hi,
                                       __nv_bfloat16* __restrict__ lo,
                                       int K, int N)
{
    __shared__ float t[32][33];
    const int nb = blockIdx.x * 32, kb = blockIdx.y * 32;
    const int tx = threadIdx.x, ty = threadIdx.y;
#pragma unroll
    for (int j = 0; j < 4; j++)
        t[ty + j * 8][tx] = W[(size_t)(kb + ty + j * 8) * N + nb + tx];
    __syncthreads();
#pragma unroll
    for (int j = 0; j < 4; j++) {
        const int n = nb + ty + j * 8;
        const float v = t[tx][ty + j * 8];
        __nv_bfloat16 h = __float2bfloat16(v);
        hi[(size_t)n * K + kb + tx] = h;
        lo[(size_t)n * K + kb + tx] = __float2bfloat16(v - __bfloat162float(h));
    }
}

// ---------------------------------------------------------------------------
// RoPE (interleaved pairs)
// ---------------------------------------------------------------------------
__global__ void rope_kernel(float* __restrict__ t,
                            const float* __restrict__ fcos,
                            const float* __restrict__ fsin,
                            int nheads, int npairs_total)
{
    int gid = blockIdx.x * blockDim.x + threadIdx.x;
    if (gid >= npairs_total) return;
    int i    = gid & 63;
    int rest = gid >> 6;
    int hh   = rest % nheads;
    int tok  = rest / nheads;
    int s    = tok & (SEQL - 1);
    float c  = fcos[s * 64 + i];
    float sn = fsin[s * 64 + i];
    size_t base = ((size_t)tok * nheads + hh) * HEADD + 2 * i;
    float a = t[base], b = t[base + 1];
    t[base]     = a * c - b * sn;
    t[base + 1] = a * sn + b * c;
}

// ---------------------------------------------------------------------------
// Fused causal flash attention, fp32 (unchanged)
// ---------------------------------------------------------------------------
#define FA_BR 64
#define FA_BC 64
#define KPAD  132

__global__ void __launch_bounds__(256) flash_kernel(
    const float* __restrict__ qin, const float* __restrict__ kin,
    const float* __restrict__ vin, float* __restrict__ oout)
{
    extern __shared__ float smf[];
    float* Qs = smf;
    float* Ks = Qs + FA_BR * HEADD;
    float* Vs = Ks + FA_BC * KPAD;
    float* Ps = Vs + FA_BC * HEADD;

    const int z  = blockIdx.y;
    const int b  = z >> 5;
    const int h  = z & 31;
    const int kv = h >> 2;
    const int qt = blockIdx.x;
    const int q0 = qt * FA_BR;
    const int tid = threadIdx.x;
    const int tx = tid & 15;
    const int ty = tid >> 4;

    const float* Qg = qin + (size_t)b * SEQL * QD  + (size_t)h  * HEADD;
    const float* Kg = kin + (size_t)b * SEQL * KVD + (size_t)kv * HEADD;
    const float* Vg = vin + (size_t)b * SEQL * KVD + (size_t)kv * HEADD;
    float*       Og = oout + (size_t)b * SEQL * QD + (size_t)h  * HEADD;

    for (int idx = tid; idx < FA_BR * 32; idx += 256) {
        int r = idx >> 5, c4 = (idx & 31) << 2;
        *(float4*)&Qs[r * HEADD + c4] =
            *(const float4*)&Qg[(size_t)(q0 + r) * QD + c4];
    }

    float m[4], l[4], O[4][8];
#pragma unroll
    for (int i = 0; i < 4; i++) {
        m[i] = -1e30f; l[i] = 0.f;
#pragma unroll
        for (int d = 0; d < 8; d++) O[i][d] = 0.f;
    }

    for (int kt = 0; kt <= qt; kt++) {
        const int s0 = kt * FA_BC;
        __syncthreads();
        for (int idx = tid; idx < FA_BC * 32; idx += 256) {
            int r = idx >> 5, c4 = (idx & 31) << 2;
            *(float4*)&Ks[r * KPAD  + c4] =
                *(const float4*)&Kg[(size_t)(s0 + r) * KVD + c4];
            *(float4*)&Vs[r * HEADD + c4] =
                *(const float4*)&Vg[(size_t)(s0 + r) * KVD + c4];
        }
        __syncthreads();

        float acc[4][4];
#pragma unroll
        for (int i = 0; i < 4; i++)
#pragma unroll
            for (int j = 0; j < 4; j++) acc[i][j] = 0.f;

        for (int k4 = 0; k4 < HEADD; k4 += 4) {
            float4 qv[4], kvv[4];
#pragma unroll
            for (int i = 0; i < 4; i++)
                qv[i] = *(const float4*)&Qs[(ty * 4 + i) * HEADD + k4];
#pragma unroll
            for (int j = 0; j < 4; j++)
                kvv[j] = *(const float4*)&Ks[(tx * 4 + j) * KPAD + k4];
#pragma unroll
            for (int i = 0; i < 4; i++)
#pragma unroll
                for (int j = 0; j < 4; j++) {
                    acc[i][j] = fmaf(qv[i].x, kvv[j].x, acc[i][j]);
                    acc[i][j] = fmaf(qv[i].y, kvv[j].y, acc[i][j]);
                    acc[i][j] = fmaf(qv[i].z, kvv[j].z, acc[i][j]);
                    acc[i][j] = fmaf(qv[i].w, kvv[j].w, acc[i][j]);
                }
        }

        const bool diag = (kt == qt);
#pragma unroll
        for (int i = 0; i < 4; i++) {
            const int r = ty * 4 + i;
#pragma unroll
            for (int j = 0; j < 4; j++) {
                float s = acc[i][j] * 0.08838834764831843f;
                if (diag && (tx * 4 + j > r)) s = -1e30f;
                acc[i][j] = s;
            }
            float tm = fmaxf(fmaxf(acc[i][0], acc[i][1]),
                             fmaxf(acc[i][2], acc[i][3]));
#pragma unroll
            for (int o = 8; o; o >>= 1)
                tm = fmaxf(tm, __shfl_xor_sync(0xffffffffu, tm, o));
            float mnew = fmaxf(m[i], tm);
            float scale = __expf(m[i] - mnew);
            float4 p;
            p.x = __expf(acc[i][0] - mnew);
            p.y = __expf(acc[i][1] - mnew);
            p.z = __expf(acc[i][2] - mnew);
            p.w = __expf(acc[i][3] - mnew);
            float ts = p.x + p.y + p.z + p.w;
#pragma unroll
            for (int o = 8; o; o >>= 1)
                ts += __shfl_xor_sync(0xffffffffu, ts, o);
            l[i] = l[i] * scale + ts;
            m[i] = mnew;
#pragma unroll
            for (int d = 0; d < 8; d++) O[i][d] *= scale;
            *(float4*)&Ps[r * FA_BC + tx * 4] = p;
        }
        __syncthreads();

        for (int c = 0; c < FA_BC; c++) {
            float4 va = *(const float4*)&Vs[c * HEADD + tx * 8];
            float4 vb = *(const float4*)&Vs[c * HEADD + tx * 8 + 4];
#pragma unroll
            for (int i = 0; i < 4; i++) {
                float p = Ps[(ty * 4 + i) * FA_BC + c];
                O[i][0] = fmaf(p, va.x, O[i][0]);
                O[i][1] = fmaf(p, va.y, O[i][1]);
                O[i][2] = fmaf(p, va.z, O[i][2]);
                O[i][3] = fmaf(p, va.w, O[i][3]);
                O[i][4] = fmaf(p, vb.x, O[i][4]);
                O[i][5] = fmaf(p, vb.y, O[i][5]);
                O[i][6] = fmaf(p, vb.z, O[i][6]);
                O[i][7] = fmaf(p, vb.w, O[i][7]);
            }
        }
    }

#pragma unroll
    for (int i = 0; i < 4; i++) {
        const int r = ty * 4 + i;
        const float invl = 1.0f / l[i];
        float4 oa, ob;
        oa.x = O[i][0] * invl; oa.y = O[i][1] * invl;
        oa.z = O[i][2] * invl; oa.w = O[i][3] * invl;
        ob.x = O[i][4] * invl; ob.y = O[i][5] * invl;
        ob.z = O[i][6] * invl; ob.w = O[i][7] * invl;
        *(float4*)&Og[(size_t)(q0 + r) * QD + tx * 8]     = oa;
        *(float4*)&Og[(size_t)(q0 + r) * QD + tx * 8 + 4] = ob;
    }
}

// ---------------------------------------------------------------------------
// f1 = silu(f1) * f3
// ---------------------------------------------------------------------------
__global__ void silu_mul_kernel(float* __restrict__ f1, const float* __restrict__ f3,
                                size_t n)
{
    size_t stride = (size_t)gridDim.x * blockDim.x;
    for (size_t i = (size_t)blockIdx.x * blockDim.x + threadIdx.x; i < n; i += stride) {
        float a = f1[i];
        f1[i] = a / (1.0f + __expf(-a)) * f3[i];
    }
}

// ---------------------------------------------------------------------------
// kernel_launch
// ---------------------------------------------------------------------------
extern "C" void kernel_launch(void* const* d_in, const int* in_sizes, int n_in,
                              void* d_out, int out_size)
{
    const float* x    = (const float*)d_in[0];
    /* d_in[1] = mask (unused; causal handled analytically) */
    const float* fcos = (const float*)d_in[2];
    const float* fsin = (const float*)d_in[3];
    const float* wq   = (const float*)d_in[4];
    const float* wk   = (const float*)d_in[5];
    const float* wv   = (const float*)d_in[6];
    const float* wo   = (const float*)d_in[7];
    const float* w1   = (const float*)d_in[8];
    const float* w2   = (const float*)d_in[9];
    const float* w3   = (const float*)d_in[10];
    float* out = (float*)d_out;

    float *q, *k, *v, *h, *f1, *f3;
    __nv_bfloat16 *ahi, *alo, *whi, *wlo;
    cudaGetSymbolAddress((void**)&q,   g_q);
    cudaGetSymbolAddress((void**)&k,   g_k);
    cudaGetSymbolAddress((void**)&v,   g_v);
    cudaGetSymbolAddress((void**)&h,   g_h);
    cudaGetSymbolAddress((void**)&f1,  g_f1);
    cudaGetSymbolAddress((void**)&f3,  g_f3);
    cudaGetSymbolAddress((void**)&ahi, g_ahi);
    cudaGetSymbolAddress((void**)&alo, g_alo);
    cudaGetSymbolAddress((void**)&whi, g_whi);
    cudaGetSymbolAddress((void**)&wlo, g_wlo);

    static int attr_done = 0;
    if (!attr_done) {
        cudaFuncSetAttribute(mma_gemm,
            cudaFuncAttributeMaxDynamicSharedMemorySize, GEMM_SMEM);
        const int fa_sm = (FA_BR * HEADD + FA_BC * KPAD + FA_BC * HEADD +
                           FA_BR * FA_BC) * (int)sizeof(float);
        cudaFuncSetAttribute(flash_kernel,
            cudaFuncAttributeMaxDynamicSharedMemorySize, fa_sm);
        attr_done = 1;
    }
    const int fa_smem = (FA_BR * HEADD + FA_BC * KPAD + FA_BC * HEADD +
                         FA_BR * FA_BC) * (int)sizeof(float);

    const dim3 tb(32, 8);

    // x -> bf16 split (shared by Q/K/V projections)
    split_kernel<<<2048, 256>>>(x, ahi, alo, (size_t)TOK * DIM);

    // Q = x @ wq
    split_transpose_kernel<<<dim3(QD / 32, DIM / 32), tb>>>(wq, whi, wlo, DIM, QD);
    mma_gemm<<<dim3(QD / 128, TOK / 128), 256, GEMM_SMEM>>>(ahi, alo, whi, wlo, nullptr, q, DIM, QD);
    // K = x @ wk
    split_transpose_kernel<<<dim3(KVD / 32, DIM / 32), tb>>>(wk, whi, wlo, DIM, KVD);
    mma_gemm<<<dim3(KVD / 128, TOK / 128), 256, GEMM_SMEM>>>(ahi, alo, whi, wlo, nullptr, k, DIM, KVD);
    // V = x @ wv
    split_transpose_kernel<<<dim3(KVD / 32, DIM / 32), tb>>>(wv, whi, wlo, DIM, KVD);
    mma_gemm<<<dim3(KVD / 128, TOK / 128), 256, GEMM_SMEM>>>(ahi, alo, whi, wlo, nullptr, v, DIM, KVD);

    // RoPE
    {
        int nq  = TOK * NH  * 64;
        int nk2 = TOK * NKV * 64;
        rope_kernel<<<(nq + 255) / 256, 256>>>(q, fcos, fsin, NH,  nq);
        rope_kernel<<<(nk2 + 255) / 256, 256>>>(k, fcos, fsin, NKV, nk2);
    }

    // fused causal attention; output overwrites q
    flash_kernel<<<dim3(SEQL / FA_BR, BATCH * NH), 256, fa_smem>>>(q, k, v, q);

    // h = x + attn @ wo
    split_kernel<<<2048, 256>>>(q, ahi, alo, (size_t)TOK * QD);
    split_transpose_kernel<<<dim3(DIM / 32, QD / 32), tb>>>(wo, whi, wlo, QD, DIM);
    mma_gemm<<<dim3(DIM / 128, TOK / 128), 256, GEMM_SMEM>>>(ahi, alo, whi, wlo, x, h, QD, DIM);

    // FFN
    split_kernel<<<2048, 256>>>(h, ahi, alo, (size_t)TOK * DIM);
    split_transpose_kernel<<<dim3(HIDDEN / 32, DIM / 32), tb>>>(w1, whi, wlo, DIM, HIDDEN);
    mma_gemm<<<dim3(HIDDEN / 128, TOK / 128), 256, GEMM_SMEM>>>(ahi, alo, whi, wlo, nullptr, f1, DIM, HIDDEN);
    split_transpose_kernel<<<dim3(HIDDEN / 32, DIM / 32), tb>>>(w3, whi, wlo, DIM, HIDDEN);
    mma_gemm<<<dim3(HIDDEN / 128, TOK / 128), 256, GEMM_SMEM>>>(ahi, alo, whi, wlo, nullptr, f3, DIM, HIDDEN);

    silu_mul_kernel<<<4096, 256>>>(f1, f3, (size_t)TOK * HIDDEN);

    // out = h + gated @ w2
    split_kernel<<<4096, 256>>>(f1, ahi, alo, (size_t)TOK * HIDDEN);
    split_transpose_kernel<<<dim3(DIM / 32, HIDDEN / 32), tb>>>(w2, whi, wlo, HIDDEN, DIM);
    mma_gemm<<<dim3(DIM / 128, TOK / 128), 256, GEMM_SMEM>>>(ahi, alo, whi, wlo, h, out, HIDDEN, DIM);
}

// round 7
// speedup vs baseline: 1.2540x; 1.2540x over previous
#include <cuda_runtime.h>
#include <cuda_bf16.h>
#include <math.h>
#include <stddef.h>
#include <stdint.h>

// ---------------------------------------------------------------------------
// Problem constants
// ---------------------------------------------------------------------------
#define BATCH   2
#define SEQL    2048
#define DIM     4096
#define NH      32
#define NKV     8
#define HEADD   128
#define HIDDEN  11008
#define TOK     (BATCH * SEQL)        /* 4096 */
#define QD      (NH  * HEADD)         /* 4096 */
#define KVD     (NKV * HEADD)         /* 1024 */
#define MAXEL   ((size_t)TOK * HIDDEN)

// ---------------------------------------------------------------------------
// Scratch (static device globals; allocation-free per harness rules)
// ---------------------------------------------------------------------------
__device__ float g_q [(size_t)TOK * QD];
__device__ float g_k [(size_t)TOK * KVD];
__device__ float g_v [(size_t)TOK * KVD];
__device__ float g_h [(size_t)TOK * DIM];
__device__ float g_f1[(size_t)TOK * HIDDEN];
__device__ float g_f3[(size_t)TOK * HIDDEN];
__device__ __nv_bfloat16 g_ahi[MAXEL];
__device__ __nv_bfloat16 g_alo[MAXEL];
__device__ __nv_bfloat16 g_whi[MAXEL];
__device__ __nv_bfloat16 g_wlo[MAXEL];
// flash attention bf16 operands
__device__ __nv_bfloat16 g_qhi[(size_t)TOK * QD];
__device__ __nv_bfloat16 g_qlo[(size_t)TOK * QD];
__device__ __nv_bfloat16 g_khi[(size_t)TOK * KVD];
__device__ __nv_bfloat16 g_klo[(size_t)TOK * KVD];
__device__ __nv_bfloat16 g_vthi[(size_t)TOK * KVD];  // [B][NKV][HEADD][SEQL]
__device__ __nv_bfloat16 g_vtlo[(size_t)TOK * KVD];

// ---------------------------------------------------------------------------
// PTX helpers (sm_100-safe: cp.async / ldmatrix / mma.sync only)
// ---------------------------------------------------------------------------
__device__ __forceinline__ uint32_t smem_u32(const void* p) {
    uint32_t a;
    asm("{ .reg .u64 t; cvta.to.shared.u64 t, %1; cvt.u32.u64 %0, t; }"
        : "=r"(a) : "l"(p));
    return a;
}
#define CP_ASYNC16(dst, src) \
    asm volatile("cp.async.cg.shared.global [%0], [%1], 16;" \
                 :: "r"(dst), "l"(src) : "memory")
#define CP_COMMIT() asm volatile("cp.async.commit_group;" ::: "memory")
#define CP_WAIT0()  asm volatile("cp.async.wait_group 0;" ::: "memory")
#define CP_WAIT1()  asm volatile("cp.async.wait_group 1;" ::: "memory")

#define LDMX4(r0, r1, r2, r3, addr) \
    asm volatile("ldmatrix.sync.aligned.m8n8.x4.shared.b16 {%0,%1,%2,%3}, [%4];" \
                 : "=r"(r0), "=r"(r1), "=r"(r2), "=r"(r3) : "r"(addr))

#define MMA16816(c0, c1, c2, c3, a0, a1, a2, a3, b0, b1) \
    asm volatile("mma.sync.aligned.m16n8k16.row.col.f32.bf16.bf16.f32 " \
                 "{%0,%1,%2,%3}, {%4,%5,%6,%7}, {%8,%9}, {%0,%1,%2,%3};" \
                 : "+f"(c0), "+f"(c1), "+f"(c2), "+f"(c3) \
                 : "r"(a0), "r"(a1), "r"(a2), "r"(a3), "r"(b0), "r"(b1))

__device__ __forceinline__ uint32_t swz(uint32_t o) { return o ^ ((o >> 3) & 0x70); }

__device__ __forceinline__ uint32_t pack_bf16x2(float x, float y) {
    __nv_bfloat162 t = __floats2bfloat162_rn(x, y);
    return *(uint32_t*)&t;
}

// ---------------------------------------------------------------------------
// bf16 HMMA GEMM (round-4 config: 2-stage, 64 KB smem, 2 CTAs/SM)
// ---------------------------------------------------------------------------
#define STG 32768
#define GEMM_SMEM 65536

__global__ void __launch_bounds__(256) mma_gemm(
    const __nv_bfloat16* __restrict__ Ahi, const __nv_bfloat16* __restrict__ Alo,
    const __nv_bfloat16* __restrict__ Bhi, const __nv_bfloat16* __restrict__ Blo,
    const float* __restrict__ resid, float* __restrict__ C,
    int K, int ldc)
{
    extern __shared__ char smc[];
    const uint32_t sbase = smem_u32(smc);
    const int tid   = threadIdx.x;
    const int lane  = tid & 31;
    const int wid   = tid >> 5;
    const int warpM = wid >> 2;
    const int warpN = wid & 3;
    const int m0 = blockIdx.y * 128;
    const int n0 = blockIdx.x * 128;

    const int nk = K >> 6;
    const int NC = 3 * nk;

    float acc[4][4][4];
#pragma unroll
    for (int mt = 0; mt < 4; mt++)
#pragma unroll
        for (int nt = 0; nt < 4; nt++)
#pragma unroll
            for (int e = 0; e < 4; e++) acc[mt][nt][e] = 0.f;

    auto load_chunk = [&](int c, int stage) {
        const int p  = c / nk;
        const int k0 = (c - p * nk) << 6;
        const __nv_bfloat16* As = (p == 2) ? Alo : Ahi;
        const __nv_bfloat16* Bs = (p == 1) ? Blo : Bhi;
        const uint32_t uA = sbase + stage * STG;
        const uint32_t uB = uA + 16384;
#pragma unroll
        for (int it = 0; it < 4; it++) {
            const int idx = tid + it * 256;
            const int r  = idx >> 3;
            const int cc = idx & 7;
            uint32_t o = swz((uint32_t)(r * 128 + cc * 16));
            CP_ASYNC16(uA + o, As + (size_t)(m0 + r) * K + k0 + cc * 8);
            CP_ASYNC16(uB + o, Bs + (size_t)(n0 + r) * K + k0 + cc * 8);
        }
    };

    auto compute_chunk = [&](int stage) {
        const uint32_t uA = sbase + stage * STG;
        const uint32_t uB = uA + 16384;
#pragma unroll
        for (int ks = 0; ks < 4; ks++) {
            const int kb = ks * 32;
            uint32_t a[4][4];
#pragma unroll
            for (int mt = 0; mt < 4; mt++) {
                const int r = warpM * 64 + mt * 16 + (lane & 15);
                uint32_t o = swz((uint32_t)(r * 128 + kb + ((lane >> 4) << 4)));
                LDMX4(a[mt][0], a[mt][1], a[mt][2], a[mt][3], uA + o);
            }
            uint32_t bf[2][4];
#pragma unroll
            for (int g = 0; g < 2; g++) {
                const int r = warpN * 32 + g * 16 + (lane & 7) + ((lane >> 4) << 3);
                uint32_t o = swz((uint32_t)(r * 128 + kb + (((lane >> 3) & 1) << 4)));
                LDMX4(bf[g][0], bf[g][1], bf[g][2], bf[g][3], uB + o);
            }
#pragma unroll
            for (int mt = 0; mt < 4; mt++)
#pragma unroll
                for (int nt = 0; nt < 4; nt++) {
                    const uint32_t b0 = bf[nt >> 1][(nt & 1) * 2];
                    const uint32_t b1 = bf[nt >> 1][(nt & 1) * 2 + 1];
                    MMA16816(acc[mt][nt][0], acc[mt][nt][1],
                             acc[mt][nt][2], acc[mt][nt][3],
                             a[mt][0], a[mt][1], a[mt][2], a[mt][3], b0, b1);
                }
        }
    };

    load_chunk(0, 0);
    CP_COMMIT();

    for (int i = 0; i < NC; i++) {
        const int b = i & 1;
        if (i + 1 < NC) {
            load_chunk(i + 1, b ^ 1);
            CP_COMMIT();
            CP_WAIT1();
        } else {
            CP_WAIT0();
        }
        __syncthreads();
        compute_chunk(b);
        __syncthreads();
    }

    const int g  = lane >> 2;
    const int tg = lane & 3;
#pragma unroll
    for (int mt = 0; mt < 4; mt++) {
        const int row = m0 + warpM * 64 + mt * 16 + g;
#pragma unroll
        for (int nt = 0; nt < 4; nt++) {
            const int col = n0 + warpN * 32 + nt * 8 + tg * 2;
            const size_t i0 = (size_t)row * ldc + col;
            const size_t i1 = (size_t)(row + 8) * ldc + col;
            float2 v0 = make_float2(acc[mt][nt][0], acc[mt][nt][1]);
            float2 v1 = make_float2(acc[mt][nt][2], acc[mt][nt][3]);
            if (resid) {
                float2 r0 = *(const float2*)(resid + i0);
                float2 r1 = *(const float2*)(resid + i1);
                v0.x += r0.x; v0.y += r0.y;
                v1.x += r1.x; v1.y += r1.y;
            }
            *(float2*)(C + i0) = v0;
            *(float2*)(C + i1) = v1;
        }
    }
}

// ---------------------------------------------------------------------------
// fp32 -> bf16 hi/lo split (elementwise)
// ---------------------------------------------------------------------------
__global__ void split_kernel(const float* __restrict__ src,
                             __nv_bfloat16* __restrict__ hi,
                             __nv_bfloat16* __restrict__ lo, size_t n)
{
    const size_t stride = (size_t)gridDim.x * blockDim.x;
    for (size_t i = (size_t)blockIdx.x * blockDim.x + threadIdx.x; i < n; i += stride) {
        float v = src[i];
        __nv_bfloat16 h = __float2bfloat16(v);
        hi[i] = h;
        lo[i] = __float2bfloat16(v - __bfloat162float(h));
    }
}

// W [K,N] fp32 -> W^T [N,K] bf16 hi/lo.  grid=(N/32, K/32), block=(32,8)
__global__ void split_transpose_kernel(const float* __restrict__ W,
                                       __nv_bfloat16* __restrict__ hi,
                                       __nv_bfloat16* __restrict__ lo,
                                       int K, int N)
{
    __shared__ float t[32][33];
    const int nb = blockIdx.x * 32, kb = blockIdx.y * 32;
    const int tx = threadIdx.x, ty = threadIdx.y;
#pragma unroll
    for (int j = 0; j < 4; j++)
        t[ty + j * 8][tx] = W[(size_t)(kb + ty + j * 8) * N + nb + tx];
    __syncthreads();
#pragma unroll
    for (int j = 0; j < 4; j++) {
        const int n = nb + ty + j * 8;
        const float v = t[tx][ty + j * 8];
        __nv_bfloat16 h = __float2bfloat16(v);
        hi[(size_t)n * K + kb + tx] = h;
        lo[(size_t)n * K + kb + tx] = __float2bfloat16(v - __bfloat162float(h));
    }
}

// v [tok][kv*128+d] fp32 -> vt [(b*NKV+kv)*HEADD + d][s] bf16 hi/lo
// grid = (SEQL/32, HEADD/32, BATCH*NKV), block = (32,8)
__global__ void vt_split_kernel(const float* __restrict__ v,
                                __nv_bfloat16* __restrict__ hi,
                                __nv_bfloat16* __restrict__ lo)
{
    __shared__ float t[32][33];
    const int z = blockIdx.z, b = z >> 3, kvh = z & 7;
    const int sb = blockIdx.x * 32, db = blockIdx.y * 32;
    const int tx = threadIdx.x, ty = threadIdx.y;
#pragma unroll
    for (int j = 0; j < 4; j++)
        t[ty + j * 8][tx] =
            v[(size_t)(b * SEQL + sb + ty + j * 8) * KVD + kvh * HEADD + db + tx];
    __syncthreads();
#pragma unroll
    for (int j = 0; j < 4; j++) {
        const int d = db + ty + j * 8, s = sb + tx;
        const float val = t[tx][ty + j * 8];
        __nv_bfloat16 h = __float2bfloat16(val);
        const size_t o = ((size_t)(b * NKV + kvh) * HEADD + d) * SEQL + s;
        hi[o] = h;
        lo[o] = __float2bfloat16(val - __bfloat162float(h));
    }
}

// ---------------------------------------------------------------------------
// RoPE (interleaved pairs)
// ---------------------------------------------------------------------------
__global__ void rope_kernel(float* __restrict__ t,
                            const float* __restrict__ fcos,
                            const float* __restrict__ fsin,
                            int nheads, int npairs_total)
{
    int gid = blockIdx.x * blockDim.x + threadIdx.x;
    if (gid >= npairs_total) return;
    int i    = gid & 63;
    int rest = gid >> 6;
    int hh   = rest % nheads;
    int tok  = rest / nheads;
    int s    = tok & (SEQL - 1);
    float c  = fcos[s * 64 + i];
    float sn = fsin[s * 64 + i];
    size_t base = ((size_t)tok * nheads + hh) * HEADD + 2 * i;
    float a = t[base], b = t[base + 1];
    t[base]     = a * c - b * sn;
    t[base + 1] = a * sn + b * c;
}

// ---------------------------------------------------------------------------
// HMMA flash attention, causal, 3-pass hi/lo for both QK^T and PV.
// BR=128, BC=64; 8 warps (16 q-rows each); double-buffered K/V via cp.async.
// smem: Q hi/lo 64K + 2 KV stages x 64K = 192K. grid=(SEQL/128, B*NH).
// ---------------------------------------------------------------------------
#define SQ_HI 0
#define SQ_LO 32768
#define SKV0  65536
#define KVSTG 65536
#define FLASH_SMEM (SKV0 + 2 * KVSTG)   /* 196608 */

__global__ void __launch_bounds__(256) flash_mma_kernel(
    const __nv_bfloat16* __restrict__ qhi, const __nv_bfloat16* __restrict__ qlo,
    const __nv_bfloat16* __restrict__ khi, const __nv_bfloat16* __restrict__ klo,
    const __nv_bfloat16* __restrict__ vthi, const __nv_bfloat16* __restrict__ vtlo,
    float* __restrict__ oout)
{
    extern __shared__ char smc[];
    const uint32_t sb = smem_u32(smc);
    const int z = blockIdx.y, b = z >> 5, h = z & 31, kv = h >> 2;
    const int qt = blockIdx.x, q0 = qt * 128;
    const int tid = threadIdx.x, lane = tid & 31, w = tid >> 5;
    const int g = lane >> 2, tg = lane & 3;

    // ---- Q load (one commit group)
    {
        const __nv_bfloat16* qh = qhi + (size_t)(b * SEQL + q0) * QD + h * HEADD;
        const __nv_bfloat16* ql = qlo + (size_t)(b * SEQL + q0) * QD + h * HEADD;
#pragma unroll
        for (int it = 0; it < 8; it++) {
            const int idx = tid + it * 256;          // 0..2047
            const int sub = idx >> 10, rem = idx & 1023;
            const int r = rem >> 3, cc = rem & 7;
            const uint32_t o = swz((uint32_t)(r * 128 + cc * 16));
            const size_t src = (size_t)r * QD + sub * 64 + cc * 8;
            CP_ASYNC16(sb + SQ_HI + sub * 16384 + o, qh + src);
            CP_ASYNC16(sb + SQ_LO + sub * 16384 + o, ql + src);
        }
        CP_COMMIT();
    }

    const int nkt = 2 * qt + 2;
    auto load_kv = [&](int kt) {
        const uint32_t base = sb + SKV0 + (kt & 1) * KVSTG;
        const int s0 = kt * 64;
        const __nv_bfloat16* kh = khi + (size_t)(b * SEQL + s0) * KVD + kv * HEADD;
        const __nv_bfloat16* kl = klo + (size_t)(b * SEQL + s0) * KVD + kv * HEADD;
#pragma unroll
        for (int it = 0; it < 4; it++) {
            const int idx = tid + it * 256;          // 0..1023
            const int sub = idx >> 9, rem = idx & 511;
            const int r = rem >> 3, cc = rem & 7;
            const uint32_t o = swz((uint32_t)(r * 128 + cc * 16));
            const size_t src = (size_t)r * KVD + sub * 64 + cc * 8;
            CP_ASYNC16(base + sub * 8192 + o, kh + src);
            CP_ASYNC16(base + 16384 + sub * 8192 + o, kl + src);
        }
        const __nv_bfloat16* vh = vthi + (size_t)(b * NKV + kv) * HEADD * SEQL + s0;
        const __nv_bfloat16* vl = vtlo + (size_t)(b * NKV + kv) * HEADD * SEQL + s0;
#pragma unroll
        for (int it = 0; it < 4; it++) {
            const int idx = tid + it * 256;          // 0..1023
            const int r = idx >> 3, cc = idx & 7;
            const uint32_t o = swz((uint32_t)(r * 128 + cc * 16));
            const size_t src = (size_t)r * SEQL + cc * 8;
            CP_ASYNC16(base + 32768 + o, vh + src);
            CP_ASYNC16(base + 49152 + o, vl + src);
        }
        CP_COMMIT();
    };
    load_kv(0);
    if (nkt > 1) load_kv(1);

    float m0 = -1e30f, m1 = -1e30f, l0 = 0.f, l1 = 0.f;
    float O[16][4];
#pragma unroll
    for (int nt = 0; nt < 16; nt++)
#pragma unroll
        for (int e = 0; e < 4; e++) O[nt][e] = 0.f;

    const float SC = 0.08838834764831843f;

    for (int kt = 0; kt < nkt; kt++) {
        if (kt + 1 < nkt) CP_WAIT1(); else CP_WAIT0();
        __syncthreads();
        const uint32_t base = sb + SKV0 + (kt & 1) * KVSTG;

        // ---- S = Q K^T (3 hi/lo passes fused per k-step)
        float S[8][4];
#pragma unroll
        for (int nt = 0; nt < 8; nt++)
#pragma unroll
            for (int e = 0; e < 4; e++) S[nt][e] = 0.f;

#pragma unroll
        for (int ks = 0; ks < 8; ks++) {
            const int sub = ks >> 2, kb = (ks & 3) * 32;
            const uint32_t oA =
                swz((uint32_t)((w * 16 + (lane & 15)) * 128 + kb + ((lane >> 4) << 4)));
            uint32_t aH[4], aL[4];
            LDMX4(aH[0], aH[1], aH[2], aH[3], sb + SQ_HI + sub * 16384 + oA);
            LDMX4(aL[0], aL[1], aL[2], aL[3], sb + SQ_LO + sub * 16384 + oA);
#pragma unroll
            for (int nb = 0; nb < 4; nb++) {
                const uint32_t oB = swz((uint32_t)(
                    (nb * 16 + (lane & 7) + ((lane >> 4) << 3)) * 128 +
                    kb + (((lane >> 3) & 1) << 4)));
                uint32_t bH[4], bL[4];
                LDMX4(bH[0], bH[1], bH[2], bH[3], base + sub * 8192 + oB);
                LDMX4(bL[0], bL[1], bL[2], bL[3], base + 16384 + sub * 8192 + oB);
#pragma unroll
                for (int t2 = 0; t2 < 2; t2++) {
                    const int nt = nb * 2 + t2;
                    MMA16816(S[nt][0], S[nt][1], S[nt][2], S[nt][3],
                             aH[0], aH[1], aH[2], aH[3], bH[t2 * 2], bH[t2 * 2 + 1]);
                    MMA16816(S[nt][0], S[nt][1], S[nt][2], S[nt][3],
                             aH[0], aH[1], aH[2], aH[3], bL[t2 * 2], bL[t2 * 2 + 1]);
                    MMA16816(S[nt][0], S[nt][1], S[nt][2], S[nt][3],
                             aL[0], aL[1], aL[2], aL[3], bH[t2 * 2], bH[t2 * 2 + 1]);
                }
            }
        }

        // ---- scale + causal mask + online softmax
        const int s0 = kt * 64;
        const int row0 = q0 + w * 16 + g;
#pragma unroll
        for (int nt = 0; nt < 8; nt++)
#pragma unroll
            for (int e = 0; e < 2; e++) {
                const int col = s0 + nt * 8 + tg * 2 + e;
                float v0 = S[nt][e] * SC;
                float v1 = S[nt][2 + e] * SC;
                if (col > row0)     v0 = -1e30f;
                if (col > row0 + 8) v1 = -1e30f;
                S[nt][e] = v0;
                S[nt][2 + e] = v1;
            }
        float tm0 = -1e30f, tm1 = -1e30f;
#pragma unroll
        for (int nt = 0; nt < 8; nt++) {
            tm0 = fmaxf(tm0, fmaxf(S[nt][0], S[nt][1]));
            tm1 = fmaxf(tm1, fmaxf(S[nt][2], S[nt][3]));
        }
        tm0 = fmaxf(tm0, __shfl_xor_sync(0xffffffffu, tm0, 1));
        tm0 = fmaxf(tm0, __shfl_xor_sync(0xffffffffu, tm0, 2));
        tm1 = fmaxf(tm1, __shfl_xor_sync(0xffffffffu, tm1, 1));
        tm1 = fmaxf(tm1, __shfl_xor_sync(0xffffffffu, tm1, 2));
        const float mn0 = fmaxf(m0, tm0), mn1 = fmaxf(m1, tm1);
        const float sc0 = __expf(m0 - mn0), sc1 = __expf(m1 - mn1);
        m0 = mn0; m1 = mn1;
        float ts0 = 0.f, ts1 = 0.f;
#pragma unroll
        for (int nt = 0; nt < 8; nt++) {
            S[nt][0] = __expf(S[nt][0] - mn0);
            S[nt][1] = __expf(S[nt][1] - mn0);
            S[nt][2] = __expf(S[nt][2] - mn1);
            S[nt][3] = __expf(S[nt][3] - mn1);
            ts0 += S[nt][0] + S[nt][1];
            ts1 += S[nt][2] + S[nt][3];
        }
        ts0 += __shfl_xor_sync(0xffffffffu, ts0, 1);
        ts0 += __shfl_xor_sync(0xffffffffu, ts0, 2);
        ts1 += __shfl_xor_sync(0xffffffffu, ts1, 1);
        ts1 += __shfl_xor_sync(0xffffffffu, ts1, 2);
        l0 = l0 * sc0 + ts0;
        l1 = l1 * sc1 + ts1;
#pragma unroll
        for (int nt = 0; nt < 16; nt++) {
            O[nt][0] *= sc0; O[nt][1] *= sc0;
            O[nt][2] *= sc1; O[nt][3] *= sc1;
        }

        // ---- O += P V (P fragments from registers; 3 hi/lo passes)
#pragma unroll
        for (int ks = 0; ks < 4; ks++) {
            uint32_t pH[4], pL[4];
#pragma unroll
            for (int half = 0; half < 2; half++) {
                const int st = 2 * ks + half;
                float x0 = S[st][0], y0 = S[st][1];
                float x1 = S[st][2], y1 = S[st][3];
                __nv_bfloat16 bx0 = __float2bfloat16(x0), by0 = __float2bfloat16(y0);
                __nv_bfloat16 bx1 = __float2bfloat16(x1), by1 = __float2bfloat16(y1);
                __nv_bfloat162 h0; h0.x = bx0; h0.y = by0;
                __nv_bfloat162 h1; h1.x = bx1; h1.y = by1;
                pH[half * 2 + 0] = *(uint32_t*)&h0;
                pH[half * 2 + 1] = *(uint32_t*)&h1;
                pL[half * 2 + 0] = pack_bf16x2(x0 - __bfloat162float(bx0),
                                               y0 - __bfloat162float(by0));
                pL[half * 2 + 1] = pack_bf16x2(x1 - __bfloat162float(bx1),
                                               y1 - __bfloat162float(by1));
            }
            // reorder to mma A-frag order: a0=row g k0-7, a1=row g+8 k0-7,
            // a2=row g k8-15, a3=row g+8 k8-15  ->  (pH[0],pH[1]) are tile 2ks
            // rows g,g+8 (k0-7); (pH[2],pH[3]) tile 2ks+1 (k8-15). Already correct.
#pragma unroll
            for (int nb = 0; nb < 8; nb++) {
                const uint32_t oB = swz((uint32_t)(
                    (nb * 16 + (lane & 7) + ((lane >> 4) << 3)) * 128 +
                    ks * 32 + (((lane >> 3) & 1) << 4)));
                uint32_t vH[4], vL[4];
                LDMX4(vH[0], vH[1], vH[2], vH[3], base + 32768 + oB);
                LDMX4(vL[0], vL[1], vL[2], vL[3], base + 49152 + oB);
#pragma unroll
                for (int t2 = 0; t2 < 2; t2++) {
                    const int nt = nb * 2 + t2;
                    MMA16816(O[nt][0], O[nt][1], O[nt][2], O[nt][3],
                             pH[0], pH[1], pH[2], pH[3], vH[t2 * 2], vH[t2 * 2 + 1]);
                    MMA16816(O[nt][0], O[nt][1], O[nt][2], O[nt][3],
                             pL[0], pL[1], pL[2], pL[3], vH[t2 * 2], vH[t2 * 2 + 1]);
                    MMA16816(O[nt][0], O[nt][1], O[nt][2], O[nt][3],
                             pH[0], pH[1], pH[2], pH[3], vL[t2 * 2], vL[t2 * 2 + 1]);
                }
            }
        }
        __syncthreads();   // stage fully consumed before refill
        if (kt + 2 < nkt) load_kv(kt + 2);
    }

    // ---- normalize + store
    const float il0 = 1.0f / l0, il1 = 1.0f / l1;
    float* Og = oout + (size_t)(b * SEQL) * QD + h * HEADD;
#pragma unroll
    for (int nt = 0; nt < 16; nt++) {
        const int col = nt * 8 + tg * 2;
        float2 r0 = make_float2(O[nt][0] * il0, O[nt][1] * il0);
        float2 r1 = make_float2(O[nt][2] * il1, O[nt][3] * il1);
        *(float2*)&Og[(size_t)(q0 + w * 16 + g) * QD + col]     = r0;
        *(float2*)&Og[(size_t)(q0 + w * 16 + g + 8) * QD + col] = r1;
    }
}

// ---------------------------------------------------------------------------
// f1 = silu(f1) * f3
// ---------------------------------------------------------------------------
__global__ void silu_mul_kernel(float* __restrict__ f1, const float* __restrict__ f3,
                                size_t n)
{
    size_t stride = (size_t)gridDim.x * blockDim.x;
    for (size_t i = (size_t)blockIdx.x * blockDim.x + threadIdx.x; i < n; i += stride) {
        float a = f1[i];
        f1[i] = a / (1.0f + __expf(-a)) * f3[i];
    }
}

// ---------------------------------------------------------------------------
// kernel_launch
// ---------------------------------------------------------------------------
extern "C" void kernel_launch(void* const* d_in, const int* in_sizes, int n_in,
                              void* d_out, int out_size)
{
    const float* x    = (const float*)d_in[0];
    /* d_in[1] = mask (unused; causal handled analytically) */
    const float* fcos = (const float*)d_in[2];
    const float* fsin = (const float*)d_in[3];
    const float* wq   = (const float*)d_in[4];
    const float* wk   = (const float*)d_in[5];
    const float* wv   = (const float*)d_in[6];
    const float* wo   = (const float*)d_in[7];
    const float* w1   = (const float*)d_in[8];
    const float* w2   = (const float*)d_in[9];
    const float* w3   = (const float*)d_in[10];
    float* out = (float*)d_out;

    float *q, *k, *v, *h, *f1, *f3;
    __nv_bfloat16 *ahi, *alo, *whi, *wlo;
    __nv_bfloat16 *qhi, *qlo, *khi, *klo, *vthi, *vtlo;
    cudaGetSymbolAddress((void**)&q,    g_q);
    cudaGetSymbolAddress((void**)&k,    g_k);
    cudaGetSymbolAddress((void**)&v,    g_v);
    cudaGetSymbolAddress((void**)&h,    g_h);
    cudaGetSymbolAddress((void**)&f1,   g_f1);
    cudaGetSymbolAddress((void**)&f3,   g_f3);
    cudaGetSymbolAddress((void**)&ahi,  g_ahi);
    cudaGetSymbolAddress((void**)&alo,  g_alo);
    cudaGetSymbolAddress((void**)&whi,  g_whi);
    cudaGetSymbolAddress((void**)&wlo,  g_wlo);
    cudaGetSymbolAddress((void**)&qhi,  g_qhi);
    cudaGetSymbolAddress((void**)&qlo,  g_qlo);
    cudaGetSymbolAddress((void**)&khi,  g_khi);
    cudaGetSymbolAddress((void**)&klo,  g_klo);
    cudaGetSymbolAddress((void**)&vthi, g_vthi);
    cudaGetSymbolAddress((void**)&vtlo, g_vtlo);

    static int attr_done = 0;
    if (!attr_done) {
        cudaFuncSetAttribute(mma_gemm,
            cudaFuncAttributeMaxDynamicSharedMemorySize, GEMM_SMEM);
        cudaFuncSetAttribute(flash_mma_kernel,
            cudaFuncAttributeMaxDynamicSharedMemorySize, FLASH_SMEM);
        attr_done = 1;
    }

    const dim3 tb(32, 8);

    // x -> bf16 split (shared by Q/K/V projections)
    split_kernel<<<2048, 256>>>(x, ahi, alo, (size_t)TOK * DIM);

    // QKV projections
    split_transpose_kernel<<<dim3(QD / 32, DIM / 32), tb>>>(wq, whi, wlo, DIM, QD);
    mma_gemm<<<dim3(QD / 128, TOK / 128), 256, GEMM_SMEM>>>(ahi, alo, whi, wlo, nullptr, q, DIM, QD);
    split_transpose_kernel<<<dim3(KVD / 32, DIM / 32), tb>>>(wk, whi, wlo, DIM, KVD);
    mma_gemm<<<dim3(KVD / 128, TOK / 128), 256, GEMM_SMEM>>>(ahi, alo, whi, wlo, nullptr, k, DIM, KVD);
    split_transpose_kernel<<<dim3(KVD / 32, DIM / 32), tb>>>(wv, whi, wlo, DIM, KVD);
    mma_gemm<<<dim3(KVD / 128, TOK / 128), 256, GEMM_SMEM>>>(ahi, alo, whi, wlo, nullptr, v, DIM, KVD);

    // RoPE
    {
        int nq  = TOK * NH  * 64;
        int nk2 = TOK * NKV * 64;
        rope_kernel<<<(nq + 255) / 256, 256>>>(q, fcos, fsin, NH,  nq);
        rope_kernel<<<(nk2 + 255) / 256, 256>>>(k, fcos, fsin, NKV, nk2);
    }

    // convert flash operands to bf16 hi/lo (V transposed per kv-head)
    split_kernel<<<2048, 256>>>(q, qhi, qlo, (size_t)TOK * QD);
    split_kernel<<<1024, 256>>>(k, khi, klo, (size_t)TOK * KVD);
    vt_split_kernel<<<dim3(SEQL / 32, HEADD / 32, BATCH * NKV), tb>>>(v, vthi, vtlo);

    // HMMA flash attention; output overwrites q (fp32)
    flash_mma_kernel<<<dim3(SEQL / 128, BATCH * NH), 256, FLASH_SMEM>>>(
        qhi, qlo, khi, klo, vthi, vtlo, q);

    // h = x + attn @ wo
    split_kernel<<<2048, 256>>>(q, ahi, alo, (size_t)TOK * QD);
    split_transpose_kernel<<<dim3(DIM / 32, QD / 32), tb>>>(wo, whi, wlo, QD, DIM);
    mma_gemm<<<dim3(DIM / 128, TOK / 128), 256, GEMM_SMEM>>>(ahi, alo, whi, wlo, x, h, QD, DIM);

    // FFN
    split_kernel<<<2048, 256>>>(h, ahi, alo, (size_t)TOK * DIM);
    split_transpose_kernel<<<dim3(HIDDEN / 32, DIM / 32), tb>>>(w1, whi, wlo, DIM, HIDDEN);
    mma_gemm<<<dim3(HIDDEN / 128, TOK / 128), 256, GEMM_SMEM>>>(ahi, alo, whi, wlo, nullptr, f1, DIM, HIDDEN);
    split_transpose_kernel<<<dim3(HIDDEN / 32, DIM / 32), tb>>>(w3, whi, wlo, DIM, HIDDEN);
    mma_gemm<<<dim3(HIDDEN / 128, TOK / 128), 256, GEMM_SMEM>>>(ahi, alo, whi, wlo, nullptr, f3, DIM, HIDDEN);

    silu_mul_kernel<<<4096, 256>>>(f1, f3, (size_t)TOK * HIDDEN);

    // out = h + gated @ w2
    split_kernel<<<4096, 256>>>(f1, ahi, alo, (size_t)TOK * HIDDEN);
    split_transpose_kernel<<<dim3(DIM / 32, HIDDEN / 32), tb>>>(w2, whi, wlo, HIDDEN, DIM);
    mma_gemm<<<dim3(DIM / 128, TOK / 128), 256, GEMM_SMEM>>>(ahi, alo, whi, wlo, h, out, HIDDEN, DIM);
}

// round 8
// speedup vs baseline: 1.5304x; 1.2204x over previous
#include <cuda_runtime.h>
#include <cuda_bf16.h>
#include <math.h>
#include <stddef.h>
#include <stdint.h>

// ---------------------------------------------------------------------------
// Problem constants
// ---------------------------------------------------------------------------
#define BATCH   2
#define SEQL    2048
#define DIM     4096
#define NH      32
#define NKV     8
#define HEADD   128
#define HIDDEN  11008
#define TOK     (BATCH * SEQL)        /* 4096 */
#define QD      (NH  * HEADD)         /* 4096 */
#define KVD     (NKV * HEADD)         /* 1024 */
#define MAXEL   ((size_t)TOK * HIDDEN)

// ---------------------------------------------------------------------------
// Scratch (static device globals; allocation-free per harness rules)
// ---------------------------------------------------------------------------
__device__ float g_q [(size_t)TOK * QD];
__device__ float g_k [(size_t)TOK * KVD];
__device__ float g_v [(size_t)TOK * KVD];
__device__ float g_h [(size_t)TOK * DIM];
__device__ float g_f1[(size_t)TOK * HIDDEN];
__device__ float g_f3[(size_t)TOK * HIDDEN];
__device__ __nv_bfloat16 g_ahi[MAXEL];
__device__ __nv_bfloat16 g_alo[MAXEL];
__device__ __nv_bfloat16 g_whi[MAXEL];
__device__ __nv_bfloat16 g_wlo[MAXEL];
// flash attention bf16 operands
__device__ __nv_bfloat16 g_qhi[(size_t)TOK * QD];
__device__ __nv_bfloat16 g_qlo[(size_t)TOK * QD];
__device__ __nv_bfloat16 g_khi[(size_t)TOK * KVD];
__device__ __nv_bfloat16 g_klo[(size_t)TOK * KVD];
__device__ __nv_bfloat16 g_vthi[(size_t)TOK * KVD];  // [B][NKV][HEADD][SEQL]
__device__ __nv_bfloat16 g_vtlo[(size_t)TOK * KVD];

// ---------------------------------------------------------------------------
// PTX helpers (sm_100-safe: cp.async / ldmatrix / mma.sync only)
// ---------------------------------------------------------------------------
__device__ __forceinline__ uint32_t smem_u32(const void* p) {
    uint32_t a;
    asm("{ .reg .u64 t; cvta.to.shared.u64 t, %1; cvt.u32.u64 %0, t; }"
        : "=r"(a) : "l"(p));
    return a;
}
#define CP_ASYNC16(dst, src) \
    asm volatile("cp.async.cg.shared.global [%0], [%1], 16;" \
                 :: "r"(dst), "l"(src) : "memory")
#define CP_COMMIT() asm volatile("cp.async.commit_group;" ::: "memory")
#define CP_WAIT0()  asm volatile("cp.async.wait_group 0;" ::: "memory")
#define CP_WAIT1()  asm volatile("cp.async.wait_group 1;" ::: "memory")

#define LDMX4(r0, r1, r2, r3, addr) \
    asm volatile("ldmatrix.sync.aligned.m8n8.x4.shared.b16 {%0,%1,%2,%3}, [%4];" \
                 : "=r"(r0), "=r"(r1), "=r"(r2), "=r"(r3) : "r"(addr))

#define MMA16816(c0, c1, c2, c3, a0, a1, a2, a3, b0, b1) \
    asm volatile("mma.sync.aligned.m16n8k16.row.col.f32.bf16.bf16.f32 " \
                 "{%0,%1,%2,%3}, {%4,%5,%6,%7}, {%8,%9}, {%0,%1,%2,%3};" \
                 : "+f"(c0), "+f"(c1), "+f"(c2), "+f"(c3) \
                 : "r"(a0), "r"(a1), "r"(a2), "r"(a3), "r"(b0), "r"(b1))

__device__ __forceinline__ uint32_t swz(uint32_t o) { return o ^ ((o >> 3) & 0x70); }

__device__ __forceinline__ uint32_t pack_bf16x2(float x, float y) {
    __nv_bfloat162 t = __floats2bfloat162_rn(x, y);
    return *(uint32_t*)&t;
}

// ---------------------------------------------------------------------------
// bf16 HMMA GEMM, hi/lo-FUSED: per 32-wide K chunk the smem rows pack
// [hi 64B | lo 64B] for both A and B; all three passes (AhiBhi + AhiBlo +
// AloBhi) are issued per chunk. 128x128 CTA tile, 8 warps (2Mx4N), 2-stage
// cp.async, 64 KB smem, 2 CTAs/SM.
// ---------------------------------------------------------------------------
#define STG 32768                 /* A-packed 16K + B-packed 16K */
#define GEMM_SMEM 65536

__global__ void __launch_bounds__(256, 2) mma_gemm(
    const __nv_bfloat16* __restrict__ Ahi, const __nv_bfloat16* __restrict__ Alo,
    const __nv_bfloat16* __restrict__ Bhi, const __nv_bfloat16* __restrict__ Blo,
    const float* __restrict__ resid, float* __restrict__ C,
    int K, int ldc)
{
    extern __shared__ char smc[];
    const uint32_t sbase = smem_u32(smc);
    const int tid   = threadIdx.x;
    const int lane  = tid & 31;
    const int wid   = tid >> 5;
    const int warpM = wid >> 2;
    const int warpN = wid & 3;
    const int m0 = blockIdx.y * 128;
    const int n0 = blockIdx.x * 128;

    const int NC = K >> 5;               // fused 32-wide K chunks

    float acc[4][4][4];
#pragma unroll
    for (int mt = 0; mt < 4; mt++)
#pragma unroll
        for (int nt = 0; nt < 4; nt++)
#pragma unroll
            for (int e = 0; e < 4; e++) acc[mt][nt][e] = 0.f;

    // row layout: bytes 0-63 = hi[k0..k0+31], bytes 64-127 = lo[k0..k0+31]
    auto load_chunk = [&](int c, int stage) {
        const int k0 = c << 5;
        const uint32_t uA = sbase + stage * STG;
        const uint32_t uB = uA + 16384;
#pragma unroll
        for (int it = 0; it < 4; it++) {
            const int idx = tid + it * 256;          // 0..1023
            const int r  = idx >> 3;                 // 0..127
            const int cc = idx & 7;                  // 16B slot
            const uint32_t o = swz((uint32_t)(r * 128 + cc * 16));
            const int kk = k0 + (cc & 3) * 8;
            const __nv_bfloat16* As = (cc < 4) ? Ahi : Alo;
            const __nv_bfloat16* Bs = (cc < 4) ? Bhi : Blo;
            CP_ASYNC16(uA + o, As + (size_t)(m0 + r) * K + kk);
            CP_ASYNC16(uB + o, Bs + (size_t)(n0 + r) * K + kk);
        }
    };

    auto compute_chunk = [&](int stage) {
        const uint32_t uA = sbase + stage * STG;
        const uint32_t uB = uA + 16384;
#pragma unroll
        for (int ks = 0; ks < 2; ks++) {
            const int kb = ks * 32;                  // byte offset within hi half
            uint32_t a[4][4];
            // A hi fragments
#pragma unroll
            for (int mt = 0; mt < 4; mt++) {
                const int r = warpM * 64 + mt * 16 + (lane & 15);
                const uint32_t o = swz((uint32_t)(r * 128 + kb + ((lane >> 4) << 4)));
                LDMX4(a[mt][0], a[mt][1], a[mt][2], a[mt][3], uA + o);
            }
            // B hi + lo fragments
            uint32_t bH[2][4], bL[2][4];
#pragma unroll
            for (int g = 0; g < 2; g++) {
                const int r = warpN * 32 + g * 16 + (lane & 7) + ((lane >> 4) << 3);
                const uint32_t col = kb + (((lane >> 3) & 1) << 4);
                const uint32_t oH = swz((uint32_t)(r * 128 + col));
                const uint32_t oL = swz((uint32_t)(r * 128 + 64 + col));
                LDMX4(bH[g][0], bH[g][1], bH[g][2], bH[g][3], uB + oH);
                LDMX4(bL[g][0], bL[g][1], bL[g][2], bL[g][3], uB + oL);
            }
            // pass 1: Ahi*Bhi, pass 2: Ahi*Blo
#pragma unroll
            for (int mt = 0; mt < 4; mt++)
#pragma unroll
                for (int nt = 0; nt < 4; nt++) {
                    const int gq = nt >> 1, t2 = nt & 1;
                    MMA16816(acc[mt][nt][0], acc[mt][nt][1],
                             acc[mt][nt][2], acc[mt][nt][3],
                             a[mt][0], a[mt][1], a[mt][2], a[mt][3],
                             bH[gq][t2 * 2], bH[gq][t2 * 2 + 1]);
                    MMA16816(acc[mt][nt][0], acc[mt][nt][1],
                             acc[mt][nt][2], acc[mt][nt][3],
                             a[mt][0], a[mt][1], a[mt][2], a[mt][3],
                             bL[gq][t2 * 2], bL[gq][t2 * 2 + 1]);
                }
            // A lo fragments (reuse registers of a[][])
#pragma unroll
            for (int mt = 0; mt < 4; mt++) {
                const int r = warpM * 64 + mt * 16 + (lane & 15);
                const uint32_t o = swz((uint32_t)(r * 128 + 64 + kb + ((lane >> 4) << 4)));
                LDMX4(a[mt][0], a[mt][1], a[mt][2], a[mt][3], uA + o);
            }
            // pass 3: Alo*Bhi
#pragma unroll
            for (int mt = 0; mt < 4; mt++)
#pragma unroll
                for (int nt = 0; nt < 4; nt++) {
                    const int gq = nt >> 1, t2 = nt & 1;
                    MMA16816(acc[mt][nt][0], acc[mt][nt][1],
                             acc[mt][nt][2], acc[mt][nt][3],
                             a[mt][0], a[mt][1], a[mt][2], a[mt][3],
                             bH[gq][t2 * 2], bH[gq][t2 * 2 + 1]);
                }
        }
    };

    load_chunk(0, 0);
    CP_COMMIT();

    for (int i = 0; i < NC; i++) {
        const int b = i & 1;
        if (i + 1 < NC) {
            load_chunk(i + 1, b ^ 1);
            CP_COMMIT();
            CP_WAIT1();
        } else {
            CP_WAIT0();
        }
        __syncthreads();
        compute_chunk(b);
        __syncthreads();
    }

    const int g  = lane >> 2;
    const int tg = lane & 3;
#pragma unroll
    for (int mt = 0; mt < 4; mt++) {
        const int row = m0 + warpM * 64 + mt * 16 + g;
#pragma unroll
        for (int nt = 0; nt < 4; nt++) {
            const int col = n0 + warpN * 32 + nt * 8 + tg * 2;
            const size_t i0 = (size_t)row * ldc + col;
            const size_t i1 = (size_t)(row + 8) * ldc + col;
            float2 v0 = make_float2(acc[mt][nt][0], acc[mt][nt][1]);
            float2 v1 = make_float2(acc[mt][nt][2], acc[mt][nt][3]);
            if (resid) {
                float2 r0 = *(const float2*)(resid + i0);
                float2 r1 = *(const float2*)(resid + i1);
                v0.x += r0.x; v0.y += r0.y;
                v1.x += r1.x; v1.y += r1.y;
            }
            *(float2*)(C + i0) = v0;
            *(float2*)(C + i1) = v1;
        }
    }
}

// ---------------------------------------------------------------------------
// fp32 -> bf16 hi/lo split (elementwise)
// ---------------------------------------------------------------------------
__global__ void split_kernel(const float* __restrict__ src,
                             __nv_bfloat16* __restrict__ hi,
                             __nv_bfloat16* __restrict__ lo, size_t n)
{
    const size_t stride = (size_t)gridDim.x * blockDim.x;
    for (size_t i = (size_t)blockIdx.x * blockDim.x + threadIdx.x; i < n; i += stride) {
        float v = src[i];
        __nv_bfloat16 h = __float2bfloat16(v);
        hi[i] = h;
        lo[i] = __float2bfloat16(v - __bfloat162float(h));
    }
}

// W [K,N] fp32 -> W^T [N,K] bf16 hi/lo.  grid=(N/32, K/32), block=(32,8)
__global__ void split_transpose_kernel(const float* __restrict__ W,
                                       __nv_bfloat16* __restrict__ hi,
                                       __nv_bfloat16* __restrict__ lo,
                                       int K, int N)
{
    __shared__ float t[32][33];
    const int nb = blockIdx.x * 32, kb = blockIdx.y * 32;
    const int tx = threadIdx.x, ty = threadIdx.y;
#pragma unroll
    for (int j = 0; j < 4; j++)
        t[ty + j * 8][tx] = W[(size_t)(kb + ty + j * 8) * N + nb + tx];
    __syncthreads();
#pragma unroll
    for (int j = 0; j < 4; j++) {
        const int n = nb + ty + j * 8;
        const float v = t[tx][ty + j * 8];
        __nv_bfloat16 h = __float2bfloat16(v);
        hi[(size_t)n * K + kb + tx] = h;
        lo[(size_t)n * K + kb + tx] = __float2bfloat16(v - __bfloat162float(h));
    }
}

// v [tok][kv*128+d] fp32 -> vt [(b*NKV+kv)*HEADD + d][s] bf16 hi/lo
__global__ void vt_split_kernel(const float* __restrict__ v,
                                __nv_bfloat16* __restrict__ hi,
                                __nv_bfloat16* __restrict__ lo)
{
    __shared__ float t[32][33];
    const int z = blockIdx.z, b = z >> 3, kvh = z & 7;
    const int sb = blockIdx.x * 32, db = blockIdx.y * 32;
    const int tx = threadIdx.x, ty = threadIdx.y;
#pragma unroll
    for (int j = 0; j < 4; j++)
        t[ty + j * 8][tx] =
            v[(size_t)(b * SEQL + sb + ty + j * 8) * KVD + kvh * HEADD + db + tx];
    __syncthreads();
#pragma unroll
    for (int j = 0; j < 4; j++) {
        const int d = db + ty + j * 8, s = sb + tx;
        const float val = t[tx][ty + j * 8];
        __nv_bfloat16 h = __float2bfloat16(val);
        const size_t o = ((size_t)(b * NKV + kvh) * HEADD + d) * SEQL + s;
        hi[o] = h;
        lo[o] = __float2bfloat16(val - __bfloat162float(h));
    }
}

// ---------------------------------------------------------------------------
// RoPE (interleaved pairs)
// ---------------------------------------------------------------------------
__global__ void rope_kernel(float* __restrict__ t,
                            const float* __restrict__ fcos,
                            const float* __restrict__ fsin,
                            int nheads, int npairs_total)
{
    int gid = blockIdx.x * blockDim.x + threadIdx.x;
    if (gid >= npairs_total) return;
    int i    = gid & 63;
    int rest = gid >> 6;
    int hh   = rest % nheads;
    int tok  = rest / nheads;
    int s    = tok & (SEQL - 1);
    float c  = fcos[s * 64 + i];
    float sn = fsin[s * 64 + i];
    size_t base = ((size_t)tok * nheads + hh) * HEADD + 2 * i;
    float a = t[base], b = t[base + 1];
    t[base]     = a * c - b * sn;
    t[base + 1] = a * sn + b * c;
}

// ---------------------------------------------------------------------------
// HMMA flash attention, causal, 3-pass hi/lo (unchanged from round 7)
// ---------------------------------------------------------------------------
#define SQ_HI 0
#define SQ_LO 32768
#define SKV0  65536
#define KVSTG 65536
#define FLASH_SMEM (SKV0 + 2 * KVSTG)   /* 196608 */

__global__ void __launch_bounds__(256) flash_mma_kernel(
    const __nv_bfloat16* __restrict__ qhi, const __nv_bfloat16* __restrict__ qlo,
    const __nv_bfloat16* __restrict__ khi, const __nv_bfloat16* __restrict__ klo,
    const __nv_bfloat16* __restrict__ vthi, const __nv_bfloat16* __restrict__ vtlo,
    float* __restrict__ oout)
{
    extern __shared__ char smc[];
    const uint32_t sb = smem_u32(smc);
    const int z = blockIdx.y, b = z >> 5, h = z & 31, kv = h >> 2;
    const int qt = blockIdx.x, q0 = qt * 128;
    const int tid = threadIdx.x, lane = tid & 31, w = tid >> 5;
    const int g = lane >> 2, tg = lane & 3;

    {
        const __nv_bfloat16* qh = qhi + (size_t)(b * SEQL + q0) * QD + h * HEADD;
        const __nv_bfloat16* ql = qlo + (size_t)(b * SEQL + q0) * QD + h * HEADD;
#pragma unroll
        for (int it = 0; it < 8; it++) {
            const int idx = tid + it * 256;
            const int sub = idx >> 10, rem = idx & 1023;
            const int r = rem >> 3, cc = rem & 7;
            const uint32_t o = swz((uint32_t)(r * 128 + cc * 16));
            const size_t src = (size_t)r * QD + sub * 64 + cc * 8;
            CP_ASYNC16(sb + SQ_HI + sub * 16384 + o, qh + src);
            CP_ASYNC16(sb + SQ_LO + sub * 16384 + o, ql + src);
        }
        CP_COMMIT();
    }

    const int nkt = 2 * qt + 2;
    auto load_kv = [&](int kt) {
        const uint32_t base = sb + SKV0 + (kt & 1) * KVSTG;
        const int s0 = kt * 64;
        const __nv_bfloat16* kh = khi + (size_t)(b * SEQL + s0) * KVD + kv * HEADD;
        const __nv_bfloat16* kl = klo + (size_t)(b * SEQL + s0) * KVD + kv * HEADD;
#pragma unroll
        for (int it = 0; it < 4; it++) {
            const int idx = tid + it * 256;
            const int sub = idx >> 9, rem = idx & 511;
            const int r = rem >> 3, cc = rem & 7;
            const uint32_t o = swz((uint32_t)(r * 128 + cc * 16));
            const size_t src = (size_t)r * KVD + sub * 64 + cc * 8;
            CP_ASYNC16(base + sub * 8192 + o, kh + src);
            CP_ASYNC16(base + 16384 + sub * 8192 + o, kl + src);
        }
        const __nv_bfloat16* vh = vthi + (size_t)(b * NKV + kv) * HEADD * SEQL + s0;
        const __nv_bfloat16* vl = vtlo + (size_t)(b * NKV + kv) * HEADD * SEQL + s0;
#pragma unroll
        for (int it = 0; it < 4; it++) {
            const int idx = tid + it * 256;
            const int r = idx >> 3, cc = idx & 7;
            const uint32_t o = swz((uint32_t)(r * 128 + cc * 16));
            const size_t src = (size_t)r * SEQL + cc * 8;
            CP_ASYNC16(base + 32768 + o, vh + src);
            CP_ASYNC16(base + 49152 + o, vl + src);
        }
        CP_COMMIT();
    };
    load_kv(0);
    if (nkt > 1) load_kv(1);

    float m0 = -1e30f, m1 = -1e30f, l0 = 0.f, l1 = 0.f;
    float O[16][4];
#pragma unroll
    for (int nt = 0; nt < 16; nt++)
#pragma unroll
        for (int e = 0; e < 4; e++) O[nt][e] = 0.f;

    const float SC = 0.08838834764831843f;

    for (int kt = 0; kt < nkt; kt++) {
        if (kt + 1 < nkt) CP_WAIT1(); else CP_WAIT0();
        __syncthreads();
        const uint32_t base = sb + SKV0 + (kt & 1) * KVSTG;

        float S[8][4];
#pragma unroll
        for (int nt = 0; nt < 8; nt++)
#pragma unroll
            for (int e = 0; e < 4; e++) S[nt][e] = 0.f;

#pragma unroll
        for (int ks = 0; ks < 8; ks++) {
            const int sub = ks >> 2, kb = (ks & 3) * 32;
            const uint32_t oA =
                swz((uint32_t)((w * 16 + (lane & 15)) * 128 + kb + ((lane >> 4) << 4)));
            uint32_t aH[4], aL[4];
            LDMX4(aH[0], aH[1], aH[2], aH[3], sb + SQ_HI + sub * 16384 + oA);
            LDMX4(aL[0], aL[1], aL[2], aL[3], sb + SQ_LO + sub * 16384 + oA);
#pragma unroll
            for (int nb = 0; nb < 4; nb++) {
                const uint32_t oB = swz((uint32_t)(
                    (nb * 16 + (lane & 7) + ((lane >> 4) << 3)) * 128 +
                    kb + (((lane >> 3) & 1) << 4)));
                uint32_t bH[4], bL[4];
                LDMX4(bH[0], bH[1], bH[2], bH[3], base + sub * 8192 + oB);
                LDMX4(bL[0], bL[1], bL[2], bL[3], base + 16384 + sub * 8192 + oB);
#pragma unroll
                for (int t2 = 0; t2 < 2; t2++) {
                    const int nt = nb * 2 + t2;
                    MMA16816(S[nt][0], S[nt][1], S[nt][2], S[nt][3],
                             aH[0], aH[1], aH[2], aH[3], bH[t2 * 2], bH[t2 * 2 + 1]);
                    MMA16816(S[nt][0], S[nt][1], S[nt][2], S[nt][3],
                             aH[0], aH[1], aH[2], aH[3], bL[t2 * 2], bL[t2 * 2 + 1]);
                    MMA16816(S[nt][0], S[nt][1], S[nt][2], S[nt][3],
                             aL[0], aL[1], aL[2], aL[3], bH[t2 * 2], bH[t2 * 2 + 1]);
                }
            }
        }

        const int s0 = kt * 64;
        const int row0 = q0 + w * 16 + g;
#pragma unroll
        for (int nt = 0; nt < 8; nt++)
#pragma unroll
            for (int e = 0; e < 2; e++) {
                const int col = s0 + nt * 8 + tg * 2 + e;
                float v0 = S[nt][e] * SC;
                float v1 = S[nt][2 + e] * SC;
                if (col > row0)     v0 = -1e30f;
                if (col > row0 + 8) v1 = -1e30f;
                S[nt][e] = v0;
                S[nt][2 + e] = v1;
            }
        float tm0 = -1e30f, tm1 = -1e30f;
#pragma unroll
        for (int nt = 0; nt < 8; nt++) {
            tm0 = fmaxf(tm0, fmaxf(S[nt][0], S[nt][1]));
            tm1 = fmaxf(tm1, fmaxf(S[nt][2], S[nt][3]));
        }
        tm0 = fmaxf(tm0, __shfl_xor_sync(0xffffffffu, tm0, 1));
        tm0 = fmaxf(tm0, __shfl_xor_sync(0xffffffffu, tm0, 2));
        tm1 = fmaxf(tm1, __shfl_xor_sync(0xffffffffu, tm1, 1));
        tm1 = fmaxf(tm1, __shfl_xor_sync(0xffffffffu, tm1, 2));
        const float mn0 = fmaxf(m0, tm0), mn1 = fmaxf(m1, tm1);
        const float sc0 = __expf(m0 - mn0), sc1 = __expf(m1 - mn1);
        m0 = mn0; m1 = mn1;
        float ts0 = 0.f, ts1 = 0.f;
#pragma unroll
        for (int nt = 0; nt < 8; nt++) {
            S[nt][0] = __expf(S[nt][0] - mn0);
            S[nt][1] = __expf(S[nt][1] - mn0);
            S[nt][2] = __expf(S[nt][2] - mn1);
            S[nt][3] = __expf(S[nt][3] - mn1);
            ts0 += S[nt][0] + S[nt][1];
            ts1 += S[nt][2] + S[nt][3];
        }
        ts0 += __shfl_xor_sync(0xffffffffu, ts0, 1);
        ts0 += __shfl_xor_sync(0xffffffffu, ts0, 2);
        ts1 += __shfl_xor_sync(0xffffffffu, ts1, 1);
        ts1 += __shfl_xor_sync(0xffffffffu, ts1, 2);
        l0 = l0 * sc0 + ts0;
        l1 = l1 * sc1 + ts1;
#pragma unroll
        for (int nt = 0; nt < 16; nt++) {
            O[nt][0] *= sc0; O[nt][1] *= sc0;
            O[nt][2] *= sc1; O[nt][3] *= sc1;
        }

#pragma unroll
        for (int ks = 0; ks < 4; ks++) {
            uint32_t pH[4], pL[4];
#pragma unroll
            for (int half = 0; half < 2; half++) {
                const int st = 2 * ks + half;
                float x0 = S[st][0], y0 = S[st][1];
                float x1 = S[st][2], y1 = S[st][3];
                __nv_bfloat16 bx0 = __float2bfloat16(x0), by0 = __float2bfloat16(y0);
                __nv_bfloat16 bx1 = __float2bfloat16(x1), by1 = __float2bfloat16(y1);
                __nv_bfloat162 h0; h0.x = bx0; h0.y = by0;
                __nv_bfloat162 h1; h1.x = bx1; h1.y = by1;
                pH[half * 2 + 0] = *(uint32_t*)&h0;
                pH[half * 2 + 1] = *(uint32_t*)&h1;
                pL[half * 2 + 0] = pack_bf16x2(x0 - __bfloat162float(bx0),
                                               y0 - __bfloat162float(by0));
                pL[half * 2 + 1] = pack_bf16x2(x1 - __bfloat162float(bx1),
                                               y1 - __bfloat162float(by1));
            }
#pragma unroll
            for (int nb = 0; nb < 8; nb++) {
                const uint32_t oB = swz((uint32_t)(
                    (nb * 16 + (lane & 7) + ((lane >> 4) << 3)) * 128 +
                    ks * 32 + (((lane >> 3) & 1) << 4)));
                uint32_t vH[4], vL[4];
                LDMX4(vH[0], vH[1], vH[2], vH[3], base + 32768 + oB);
                LDMX4(vL[0], vL[1], vL[2], vL[3], base + 49152 + oB);
#pragma unroll
                for (int t2 = 0; t2 < 2; t2++) {
                    const int nt = nb * 2 + t2;
                    MMA16816(O[nt][0], O[nt][1], O[nt][2], O[nt][3],
                             pH[0], pH[1], pH[2], pH[3], vH[t2 * 2], vH[t2 * 2 + 1]);
                    MMA16816(O[nt][0], O[nt][1], O[nt][2], O[nt][3],
                             pL[0], pL[1], pL[2], pL[3], vH[t2 * 2], vH[t2 * 2 + 1]);
                    MMA16816(O[nt][0], O[nt][1], O[nt][2], O[nt][3],
                             pH[0], pH[1], pH[2], pH[3], vL[t2 * 2], vL[t2 * 2 + 1]);
                }
            }
        }
        __syncthreads();
        if (kt + 2 < nkt) load_kv(kt + 2);
    }

    const float il0 = 1.0f / l0, il1 = 1.0f / l1;
    float* Og = oout + (size_t)(b * SEQL) * QD + h * HEADD;
#pragma unroll
    for (int nt = 0; nt < 16; nt++) {
        const int col = nt * 8 + tg * 2;
        float2 r0 = make_float2(O[nt][0] * il0, O[nt][1] * il0);
        float2 r1 = make_float2(O[nt][2] * il1, O[nt][3] * il1);
        *(float2*)&Og[(size_t)(q0 + w * 16 + g) * QD + col]     = r0;
        *(float2*)&Og[(size_t)(q0 + w * 16 + g + 8) * QD + col] = r1;
    }
}

// ---------------------------------------------------------------------------
// f1 = silu(f1) * f3
// ---------------------------------------------------------------------------
__global__ void silu_mul_kernel(float* __restrict__ f1, const float* __restrict__ f3,
                                size_t n)
{
    size_t stride = (size_t)gridDim.x * blockDim.x;
    for (size_t i = (size_t)blockIdx.x * blockDim.x + threadIdx.x; i < n; i += stride) {
        float a = f1[i];
        f1[i] = a / (1.0f + __expf(-a)) * f3[i];
    }
}

// ---------------------------------------------------------------------------
// kernel_launch
// ---------------------------------------------------------------------------
extern "C" void kernel_launch(void* const* d_in, const int* in_sizes, int n_in,
                              void* d_out, int out_size)
{
    const float* x    = (const float*)d_in[0];
    /* d_in[1] = mask (unused; causal handled analytically) */
    const float* fcos = (const float*)d_in[2];
    const float* fsin = (const float*)d_in[3];
    const float* wq   = (const float*)d_in[4];
    const float* wk   = (const float*)d_in[5];
    const float* wv   = (const float*)d_in[6];
    const float* wo   = (const float*)d_in[7];
    const float* w1   = (const float*)d_in[8];
    const float* w2   = (const float*)d_in[9];
    const float* w3   = (const float*)d_in[10];
    float* out = (float*)d_out;

    float *q, *k, *v, *h, *f1, *f3;
    __nv_bfloat16 *ahi, *alo, *whi, *wlo;
    __nv_bfloat16 *qhi, *qlo, *khi, *klo, *vthi, *vtlo;
    cudaGetSymbolAddress((void**)&q,    g_q);
    cudaGetSymbolAddress((void**)&k,    g_k);
    cudaGetSymbolAddress((void**)&v,    g_v);
    cudaGetSymbolAddress((void**)&h,    g_h);
    cudaGetSymbolAddress((void**)&f1,   g_f1);
    cudaGetSymbolAddress((void**)&f3,   g_f3);
    cudaGetSymbolAddress((void**)&ahi,  g_ahi);
    cudaGetSymbolAddress((void**)&alo,  g_alo);
    cudaGetSymbolAddress((void**)&whi,  g_whi);
    cudaGetSymbolAddress((void**)&wlo,  g_wlo);
    cudaGetSymbolAddress((void**)&qhi,  g_qhi);
    cudaGetSymbolAddress((void**)&qlo,  g_qlo);
    cudaGetSymbolAddress((void**)&khi,  g_khi);
    cudaGetSymbolAddress((void**)&klo,  g_klo);
    cudaGetSymbolAddress((void**)&vthi, g_vthi);
    cudaGetSymbolAddress((void**)&vtlo, g_vtlo);

    static int attr_done = 0;
    if (!attr_done) {
        cudaFuncSetAttribute(mma_gemm,
            cudaFuncAttributeMaxDynamicSharedMemorySize, GEMM_SMEM);
        cudaFuncSetAttribute(flash_mma_kernel,
            cudaFuncAttributeMaxDynamicSharedMemorySize, FLASH_SMEM);
        attr_done = 1;
    }

    const dim3 tb(32, 8);

    // x -> bf16 split (shared by Q/K/V projections)
    split_kernel<<<2048, 256>>>(x, ahi, alo, (size_t)TOK * DIM);

    // QKV projections
    split_transpose_kernel<<<dim3(QD / 32, DIM / 32), tb>>>(wq, whi, wlo, DIM, QD);
    mma_gemm<<<dim3(QD / 128, TOK / 128), 256, GEMM_SMEM>>>(ahi, alo, whi, wlo, nullptr, q, DIM, QD);
    split_transpose_kernel<<<dim3(KVD / 32, DIM / 32), tb>>>(wk, whi, wlo, DIM, KVD);
    mma_gemm<<<dim3(KVD / 128, TOK / 128), 256, GEMM_SMEM>>>(ahi, alo, whi, wlo, nullptr, k, DIM, KVD);
    split_transpose_kernel<<<dim3(KVD / 32, DIM / 32), tb>>>(wv, whi, wlo, DIM, KVD);
    mma_gemm<<<dim3(KVD / 128, TOK / 128), 256, GEMM_SMEM>>>(ahi, alo, whi, wlo, nullptr, v, DIM, KVD);

    // RoPE
    {
        int nq  = TOK * NH  * 64;
        int nk2 = TOK * NKV * 64;
        rope_kernel<<<(nq + 255) / 256, 256>>>(q, fcos, fsin, NH,  nq);
        rope_kernel<<<(nk2 + 255) / 256, 256>>>(k, fcos, fsin, NKV, nk2);
    }

    // convert flash operands to bf16 hi/lo (V transposed per kv-head)
    split_kernel<<<2048, 256>>>(q, qhi, qlo, (size_t)TOK * QD);
    split_kernel<<<1024, 256>>>(k, khi, klo, (size_t)TOK * KVD);
    vt_split_kernel<<<dim3(SEQL / 32, HEADD / 32, BATCH * NKV), tb>>>(v, vthi, vtlo);

    // HMMA flash attention; output overwrites q (fp32)
    flash_mma_kernel<<<dim3(SEQL / 128, BATCH * NH), 256, FLASH_SMEM>>>(
        qhi, qlo, khi, klo, vthi, vtlo, q);

    // h = x + attn @ wo
    split_kernel<<<2048, 256>>>(q, ahi, alo, (size_t)TOK * QD);
    split_transpose_kernel<<<dim3(DIM / 32, QD / 32), tb>>>(wo, whi, wlo, QD, DIM);
    mma_gemm<<<dim3(DIM / 128, TOK / 128), 256, GEMM_SMEM>>>(ahi, alo, whi, wlo, x, h, QD, DIM);

    // FFN
    split_kernel<<<2048, 256>>>(h, ahi, alo, (size_t)TOK * DIM);
    split_transpose_kernel<<<dim3(HIDDEN / 32, DIM / 32), tb>>>(w1, whi, wlo, DIM, HIDDEN);
    mma_gemm<<<dim3(HIDDEN / 128, TOK / 128), 256, GEMM_SMEM>>>(ahi, alo, whi, wlo, nullptr, f1, DIM, HIDDEN);
    split_transpose_kernel<<<dim3(HIDDEN / 32, DIM / 32), tb>>>(w3, whi, wlo, DIM, HIDDEN);
    mma_gemm<<<dim3(HIDDEN / 128, TOK / 128), 256, GEMM_SMEM>>>(ahi, alo, whi, wlo, nullptr, f3, DIM, HIDDEN);

    silu_mul_kernel<<<4096, 256>>>(f1, f3, (size_t)TOK * HIDDEN);

    // out = h + gated @ w2
    split_kernel<<<4096, 256>>>(f1, ahi, alo, (size_t)TOK * HIDDEN);
    split_transpose_kernel<<<dim3(DIM / 32, HIDDEN / 32), tb>>>(w2, whi, wlo, HIDDEN, DIM);
    mma_gemm<<<dim3(DIM / 128, TOK / 128), 256, GEMM_SMEM>>>(ahi, alo, whi, wlo, h, out, HIDDEN, DIM);
}